// round 2
// baseline (speedup 1.0000x reference)
#include <cuda_runtime.h>
#include <math.h>

#define NN 50000
#define EE 800000
#define MM (EE + NN)
#define HH 8
#define FF 128

// ---------------- scratch (static __device__, no allocation) ----------------
__device__ __align__(16) float g_ha[NN * FF];   // post-GEMM h (per layer)
__device__ __align__(16) float g_hb[NN * FF];   // post-aggregation h (layer output)
__device__ __align__(16) float g_es[NN * HH];
__device__ __align__(16) float g_ed[NN * HH];
__device__ __align__(16) float g_w[MM * HH];    // per-edge per-head exp weights
__device__ __align__(16) float g_dnm[NN * HH];  // softmax denominators
__device__ int   g_src[MM];                     // src ids sorted by dst (CSR)
__device__ int   g_rowptr[NN + 1];
__device__ int   g_cnt[NN];
__device__ int   g_cur[NN];
__device__ int   g_is64;                        // edge_index dtype flag

// ---------------- dtype detection ----------------
// jnp.int64 silently downcasts to int32 when x64 is disabled. Detect on device:
// interpret first 64 entries as int64; if all in [0, NN) it's genuinely int64
// (an int32 buffer read this way yields lo + hi<<32 with hi~U[0,50000), so the
// false-accept probability is (1/50000)^64 ~ 0).
__global__ void detect_kernel(const void* __restrict__ ei) {
    const long long* p64 = (const long long*)ei;
    int is64 = 1;
    for (int i = 0; i < 64; i++) {
        long long v = p64[i];  // 512B read, within buffer for either dtype
        if (v < 0 || v >= NN) { is64 = 0; break; }
    }
    g_is64 = is64;
}

__device__ __forceinline__ int load_idx(const void* __restrict__ ei, int pos) {
    if (g_is64) return (int)((const long long*)ei)[pos];
    return ((const int*)ei)[pos];
}

// ---------------- CSR build ----------------
__global__ void zero_cnt_kernel() {
    int i = blockIdx.x * blockDim.x + threadIdx.x;
    if (i < NN) g_cnt[i] = 0;
}

__global__ void count_kernel(const void* __restrict__ ei) {
    int i = blockIdx.x * blockDim.x + threadIdx.x;
    if (i >= MM) return;
    int dst = (i < EE) ? load_idx(ei, EE + i) : (i - EE);
    atomicAdd(&g_cnt[dst], 1);
}

__global__ void scan_kernel() {
    __shared__ int sums[1024];
    int tid = threadIdx.x;
    const int chunk = (NN + 1023) / 1024;
    int b = tid * chunk;
    int e = b + chunk; if (e > NN) e = NN;
    if (b > NN) b = NN;
    int s = 0;
    for (int i = b; i < e; i++) s += g_cnt[i];
    sums[tid] = s;
    __syncthreads();
    // Hillis-Steele inclusive scan
    for (int off = 1; off < 1024; off <<= 1) {
        int v = (tid >= off) ? sums[tid - off] : 0;
        __syncthreads();
        sums[tid] += v;
        __syncthreads();
    }
    int offset = (tid == 0) ? 0 : sums[tid - 1];
    for (int i = b; i < e; i++) {
        g_rowptr[i] = offset;
        g_cur[i] = offset;
        offset += g_cnt[i];
    }
    if (tid == 1023) g_rowptr[NN] = sums[1023];
}

__global__ void fill_kernel(const void* __restrict__ ei) {
    int i = blockIdx.x * blockDim.x + threadIdx.x;
    if (i >= MM) return;
    int src, dst;
    if (i < EE) { src = load_idx(ei, i); dst = load_idx(ei, EE + i); }
    else        { src = dst = i - EE; }
    int pos = atomicAdd(&g_cur[dst], 1);
    g_src[pos] = src;
}

// ---------------- fused SGEMM + attention projections ----------------
// h = X @ W  [N,128]; e_src[n,h] = <h[n,h,:], a_src[h,:]>; same for e_dst.
#define BM 64
#define BK 32

__global__ __launch_bounds__(256)
void gemm_attn_kernel(const float* __restrict__ Xext, int useExt,
                      const float* __restrict__ W,
                      const float* __restrict__ asrc,
                      const float* __restrict__ adst) {
    __shared__ float Xs[BK][BM + 1];        // transposed x tile
    __shared__ float Ws_s[BK][128];
    __shared__ float es_sh[BM][HH];
    __shared__ float ed_sh[BM][HH];

    const float* X = useExt ? Xext : g_hb;
    int tid = threadIdx.x;
    int block_m = blockIdx.x * BM;

    for (int i = tid; i < BM * HH; i += 256) {
        (&es_sh[0][0])[i] = 0.0f;
        (&ed_sh[0][0])[i] = 0.0f;
    }

    int tm = tid >> 4;   // 0..15 -> rows tm*4..+3
    int tn = tid & 15;   // cols tn*8..+7

    float acc[4][8];
#pragma unroll
    for (int i = 0; i < 4; i++)
#pragma unroll
        for (int j = 0; j < 8; j++) acc[i][j] = 0.0f;

    for (int k0 = 0; k0 < FF; k0 += BK) {
        // load W tile 32x128
#pragma unroll
        for (int i = 0; i < 4; i++) {
            int idx = (tid + i * 256) * 4;       // 0..4092
            int kk = idx >> 7, cc = idx & 127;
            float4 v = *(const float4*)&W[(k0 + kk) * 128 + cc];
            *(float4*)&Ws_s[kk][cc] = v;
        }
        // load X tile 64x32 (transposed store)
#pragma unroll
        for (int i = 0; i < 2; i++) {
            int idx = (tid + i * 256) * 4;       // 0..2044
            int m = idx >> 5, kk = idx & 31;
            int node = block_m + m;
            float4 v = make_float4(0.f, 0.f, 0.f, 0.f);
            if (node < NN) v = *(const float4*)&X[node * FF + k0 + kk];
            Xs[kk + 0][m] = v.x; Xs[kk + 1][m] = v.y;
            Xs[kk + 2][m] = v.z; Xs[kk + 3][m] = v.w;
        }
        __syncthreads();
#pragma unroll
        for (int k = 0; k < BK; k++) {
            float4 b0 = *(const float4*)&Ws_s[k][tn * 8];
            float4 b1 = *(const float4*)&Ws_s[k][tn * 8 + 4];
            float bv[8] = {b0.x, b0.y, b0.z, b0.w, b1.x, b1.y, b1.z, b1.w};
            float av[4];
#pragma unroll
            for (int i = 0; i < 4; i++) av[i] = Xs[k][tm * 4 + i];
#pragma unroll
            for (int i = 0; i < 4; i++)
#pragma unroll
                for (int j = 0; j < 8; j++) acc[i][j] += av[i] * bv[j];
        }
        __syncthreads();
    }

    // epilogue: store h, accumulate attention projections
    int h = tn >> 1;             // head for this thread's 8 cols
    float as_[8], ad_[8];
#pragma unroll
    for (int j = 0; j < 8; j++) {
        int c = (tn * 8 + j) & 15;
        as_[j] = asrc[h * 16 + c];
        ad_[j] = adst[h * 16 + c];
    }
#pragma unroll
    for (int i = 0; i < 4; i++) {
        int m = tm * 4 + i;
        int node = block_m + m;
        if (node < NN) {
            float4 o0 = make_float4(acc[i][0], acc[i][1], acc[i][2], acc[i][3]);
            float4 o1 = make_float4(acc[i][4], acc[i][5], acc[i][6], acc[i][7]);
            *(float4*)&g_ha[node * FF + tn * 8] = o0;
            *(float4*)&g_ha[node * FF + tn * 8 + 4] = o1;
            float ps = 0.f, pd = 0.f;
#pragma unroll
            for (int j = 0; j < 8; j++) { ps += acc[i][j] * as_[j]; pd += acc[i][j] * ad_[j]; }
            atomicAdd(&es_sh[m][h], ps);
            atomicAdd(&ed_sh[m][h], pd);
        }
    }
    __syncthreads();
    for (int i = tid; i < BM * HH; i += 256) {
        int node = block_m + (i >> 3);
        if (node < NN) {
            g_es[node * HH + (i & 7)] = (&es_sh[0][0])[i];
            g_ed[node * HH + (i & 7)] = (&ed_sh[0][0])[i];
        }
    }
}

// ---------------- per-dst softmax scores (warp per node, no atomics) ----------------
__global__ __launch_bounds__(256)
void attn_scores_kernel() {
    int warp = blockIdx.x * (blockDim.x >> 5) + (threadIdx.x >> 5);
    if (warp >= NN) return;
    int lane = threadIdx.x & 31;
    int head = lane & 7, slot = lane >> 3;
    int r0 = g_rowptr[warp], r1 = g_rowptr[warp + 1];
    float edv = g_ed[warp * HH + head];

    float m = -1e30f;
    for (int e = r0 + slot; e < r1; e += 4) {
        int s = g_src[e];
        float v = g_es[s * HH + head] + edv;
        v = v > 0.f ? v : 0.2f * v;
        m = fmaxf(m, v);
    }
    m = fmaxf(m, __shfl_xor_sync(0xffffffffu, m, 8));
    m = fmaxf(m, __shfl_xor_sync(0xffffffffu, m, 16));

    float d = 0.f;
    for (int e = r0 + slot; e < r1; e += 4) {
        int s = g_src[e];
        float v = g_es[s * HH + head] + edv;
        v = v > 0.f ? v : 0.2f * v;
        float w = __expf(v - m);
        d += w;
        g_w[e * HH + head] = w;
    }
    d += __shfl_xor_sync(0xffffffffu, d, 8);
    d += __shfl_xor_sync(0xffffffffu, d, 16);
    if (lane < 8) g_dnm[warp * HH + lane] = d;
}

// ---------------- weighted gather-aggregate + bias + ELU (warp per node) ----------------
__global__ __launch_bounds__(256)
void aggregate_kernel(const float* __restrict__ bias) {
    int warp = blockIdx.x * (blockDim.x >> 5) + (threadIdx.x >> 5);
    if (warp >= NN) return;
    int lane = threadIdx.x & 31;
    int head = lane >> 2;                  // 4 lanes per head, lane owns channels 4*lane..+3
    int r0 = g_rowptr[warp], r1 = g_rowptr[warp + 1];
    float inv = 1.0f / (g_dnm[warp * HH + head] + 1e-16f);

    float4 acc = make_float4(0.f, 0.f, 0.f, 0.f);
    for (int e = r0; e < r1; e++) {
        int s = g_src[e];
        float w = g_w[e * HH + head];
        float4 hv = *(const float4*)&g_ha[s * FF + lane * 4];
        acc.x += w * hv.x; acc.y += w * hv.y;
        acc.z += w * hv.z; acc.w += w * hv.w;
    }
    float4 b = *(const float4*)&bias[lane * 4];
    float4 o;
    o.x = acc.x * inv + b.x;
    o.y = acc.y * inv + b.y;
    o.z = acc.z * inv + b.z;
    o.w = acc.w * inv + b.w;
    o.x = o.x > 0.f ? o.x : expm1f(o.x);
    o.y = o.y > 0.f ? o.y : expm1f(o.y);
    o.z = o.z > 0.f ? o.z : expm1f(o.z);
    o.w = o.w > 0.f ? o.w : expm1f(o.w);
    *(float4*)&g_hb[warp * FF + lane * 4] = o;
}

// ---------------- final FC: out = h @ fc_w + fc_b  [N,16] ----------------
__global__ __launch_bounds__(256)
void final_fc_kernel(const float* __restrict__ fcw,
                     const float* __restrict__ fcb,
                     float* __restrict__ out) {
    int tid = blockIdx.x * blockDim.x + threadIdx.x;
    int node = tid >> 4;
    int c = tid & 15;
    if (node >= NN) return;
    const float* hr = g_hb + node * FF;
    float acc = fcb[c];
#pragma unroll 8
    for (int k = 0; k < FF; k++) acc += hr[k] * fcw[k * 16 + c];
    out[node * 16 + c] = acc;
}

// ---------------- launch ----------------
extern "C" void kernel_launch(void* const* d_in, const int* in_sizes, int n_in,
                              void* d_out, int out_size) {
    const float* x    = (const float*)d_in[0];
    const float* Ws   = (const float*)d_in[1];   // [3,128,128]
    const float* asrc = (const float*)d_in[2];   // [3,8,16]
    const float* adst = (const float*)d_in[3];
    const float* bias = (const float*)d_in[4];   // [3,128]
    const float* fcw  = (const float*)d_in[5];   // [128,16]
    const float* fcb  = (const float*)d_in[6];   // [16]
    const void*  ei   = (const void*)d_in[7];    // [2,E] int64 OR int32 (detected on device)
    float* out = (float*)d_out;

    // CSR build (once per launch, captured in graph)
    detect_kernel<<<1, 1>>>(ei);
    zero_cnt_kernel<<<(NN + 255) / 256, 256>>>();
    count_kernel<<<(MM + 255) / 256, 256>>>(ei);
    scan_kernel<<<1, 1024>>>();
    fill_kernel<<<(MM + 255) / 256, 256>>>(ei);

    int gemm_blocks = (NN + BM - 1) / BM;
    int warp_blocks = (NN + 7) / 8;

    for (int l = 0; l < 3; l++) {
        gemm_attn_kernel<<<gemm_blocks, 256>>>(x, l == 0 ? 1 : 0,
                                               Ws + l * 128 * 128,
                                               asrc + l * 128,
                                               adst + l * 128);
        attn_scores_kernel<<<warp_blocks, 256>>>();
        aggregate_kernel<<<warp_blocks, 256>>>(bias + l * 128);
    }

    final_fc_kernel<<<(NN * 16 + 255) / 256, 256>>>(fcw, fcb, out);
}